// round 4
// baseline (speedup 1.0000x reference)
#include <cuda_runtime.h>

#define BB 2
#define SS 2048
#define DD 1024
#define HH 16
#define HD 64
#define MASKV (-10000.0f)
#define SCALE 0.125f

// ---- scratch (allocation-free __device__ globals, referenced directly) ----
__device__ float g_Q[BB * HH * SS * HD];     // 16 MB, [b,h,s,hd]
__device__ float g_ctx[BB * SS * DD];        // 16 MB, [b,s,d]

// ============================================================
// GEMM: Y = X @ W + bias.  X [4096,1024] row-major, W [1024,1024] row-major.
// mode 0: Y -> g_Q             in [b,h,s,hd] head layout
// mode 2: X = g_ctx, Y -> Yout plain [M,N]
// mode 3: Y -> Yout            in [b,h,s,hd] head layout
// Tile 128x128, BK=8, 256 threads, 8x8 micro-tile.
// ============================================================
__global__ __launch_bounds__(256) void gemm_bias(
    const float* __restrict__ Xin, const float* __restrict__ W,
    const float* __restrict__ bias, float* __restrict__ Yout, int mode)
{
    __shared__ float As[8][132];   // [k][m], padded
    __shared__ float Bs[8][128];   // [k][n]

    const float* X = (mode == 2) ? g_ctx : Xin;

    const int tid = threadIdx.x;
    const int bm = blockIdx.y * 128;
    const int bn = blockIdx.x * 128;
    const int tx = tid & 15, ty = tid >> 4;
    const int tm = ty * 8, tn = tx * 8;

    const int arow = tid >> 1, acol = (tid & 1) * 4;   // A: 128 rows x 8 k
    const int brow = tid >> 5, bcol = (tid & 31) * 4;  // B: 8 k x 128 n

    float acc[8][8];
#pragma unroll
    for (int i = 0; i < 8; i++)
#pragma unroll
        for (int j = 0; j < 8; j++) acc[i][j] = 0.0f;

    const float* Aptr = X + (size_t)(bm + arow) * DD + acol;
    const float* Bptr = W + (size_t)brow * DD + bn + bcol;

    for (int k0 = 0; k0 < DD; k0 += 8) {
        float4 a4 = *(const float4*)(Aptr + k0);
        float4 b4 = *(const float4*)(Bptr + (size_t)k0 * DD);
        __syncthreads();
        As[acol + 0][arow] = a4.x;
        As[acol + 1][arow] = a4.y;
        As[acol + 2][arow] = a4.z;
        As[acol + 3][arow] = a4.w;
        *(float4*)&Bs[brow][bcol] = b4;
        __syncthreads();
#pragma unroll
        for (int k = 0; k < 8; k++) {
            float a[8], b[8];
            *(float4*)(a + 0) = *(const float4*)&As[k][tm];
            *(float4*)(a + 4) = *(const float4*)&As[k][tm + 4];
            *(float4*)(b + 0) = *(const float4*)&Bs[k][tn];
            *(float4*)(b + 4) = *(const float4*)&Bs[k][tn + 4];
#pragma unroll
            for (int i = 0; i < 8; i++)
#pragma unroll
                for (int j = 0; j < 8; j++)
                    acc[i][j] += a[i] * b[j];
        }
    }

    float* Y = (mode == 0) ? g_Q : Yout;

#pragma unroll
    for (int i = 0; i < 8; i++) {
        const int m = bm + tm + i;
        const int b_ = m >> 11;          // m / 2048
        const int s_ = m & (SS - 1);
#pragma unroll
        for (int j = 0; j < 8; j++) {
            const int n = bn + tn + j;
            const float v = acc[i][j] + bias[n];
            if (mode == 0 || mode == 3) {
                const int h_ = n >> 6, d_ = n & 63;
                Y[(((size_t)(b_ * HH + h_) * SS) + s_) * HD + d_] = v;
            } else {
                Y[(size_t)m * DD + n] = v;
            }
        }
    }
}

// ============================================================
// Attention: per block = one (b,h) and 16 queries.
// smem: scores[16][2048] + KV tile [64][68] + Q tile [16][68]
// ============================================================
#define QB 16
#define KT 64
#define KVP 68
#define ATTN_SMEM ((QB * SS + KT * KVP + QB * KVP) * 4)

__global__ __launch_bounds__(256) void attn_kernel(
    const float* __restrict__ K, const float* __restrict__ V,
    float* __restrict__ attw)
{
    extern __shared__ float smem[];
    float* sS  = smem;                       // 16 x 2048
    float* sKV = smem + QB * SS;             // 64 x 68
    float* sQ  = sKV + KT * KVP;             // 16 x 68

    const int tid = threadIdx.x;
    const int bh = blockIdx.y;               // b*H + h
    const int b_ = bh >> 4, h_ = bh & 15;
    const int q0 = blockIdx.x * QB;

    const float* Qb = g_Q + ((size_t)bh * SS + q0) * HD;
    const float* Kb = K + (size_t)bh * SS * HD;
    const float* Vb = V + (size_t)bh * SS * HD;

    const int nkb = ((q0 + QB - 1) / KT + 1) * KT;   // causal key extent (tile granular)

    // --- load Q tile [16][64] -> sQ (padded rows) ---
    {
        const int r = tid >> 4, c4 = (tid & 15) * 4;
        float4 v4 = *(const float4*)(Qb + (size_t)r * HD + c4);
        *(float4*)&sQ[r * KVP + c4] = v4;
    }

    // --- phase 1: scores = Q K^T * scale, causal mask, into sS ---
    {
        const int q = tid >> 4;          // 0..15 (broadcast within 16-lane group)
        const int kl = tid & 15;         // key lane; keys kl, kl+16, kl+32, kl+48
        const int qglob = q0 + q;
        for (int kt = 0; kt < nkb; kt += KT) {
            __syncthreads();
            // load K tile [64][64] -> sKV
#pragma unroll
            for (int t = 0; t < 4; t++) {
                const int idx = tid + t * 256;
                const int r = idx >> 4, c4 = (idx & 15) * 4;
                float4 v4 = *(const float4*)(Kb + (size_t)(kt + r) * HD + c4);
                *(float4*)&sKV[r * KVP + c4] = v4;
            }
            __syncthreads();

            float a0 = 0.f, a1 = 0.f, a2 = 0.f, a3 = 0.f;
#pragma unroll
            for (int d4 = 0; d4 < 16; d4++) {
                float4 qv = *(const float4*)&sQ[q * KVP + d4 * 4];
                float4 k0v = *(const float4*)&sKV[(kl +  0) * KVP + d4 * 4];
                float4 k1v = *(const float4*)&sKV[(kl + 16) * KVP + d4 * 4];
                float4 k2v = *(const float4*)&sKV[(kl + 32) * KVP + d4 * 4];
                float4 k3v = *(const float4*)&sKV[(kl + 48) * KVP + d4 * 4];
                a0 += qv.x * k0v.x + qv.y * k0v.y + qv.z * k0v.z + qv.w * k0v.w;
                a1 += qv.x * k1v.x + qv.y * k1v.y + qv.z * k1v.z + qv.w * k1v.w;
                a2 += qv.x * k2v.x + qv.y * k2v.y + qv.z * k2v.z + qv.w * k2v.w;
                a3 += qv.x * k3v.x + qv.y * k3v.y + qv.z * k3v.z + qv.w * k3v.w;
            }
            const int kg0 = kt + kl;
            sS[q * SS + kg0 +  0] = (kg0 +  0 > qglob) ? MASKV : a0 * SCALE;
            sS[q * SS + kg0 + 16] = (kg0 + 16 > qglob) ? MASKV : a1 * SCALE;
            sS[q * SS + kg0 + 32] = (kg0 + 32 > qglob) ? MASKV : a2 * SCALE;
            sS[q * SS + kg0 + 48] = (kg0 + 48 > qglob) ? MASKV : a3 * SCALE;
        }
    }
    __syncthreads();

    // --- phase 2: softmax per row + write attn_weights ---
    {
        const int warp = tid >> 5, lane = tid & 31;
        for (int r = warp * 2; r < warp * 2 + 2; r++) {
            float* row = sS + r * SS;
            float m = -1e30f;
            for (int k = lane; k < nkb; k += 32) m = fmaxf(m, row[k]);
#pragma unroll
            for (int o = 16; o; o >>= 1) m = fmaxf(m, __shfl_xor_sync(0xffffffffu, m, o));
            float sum = 0.f;
            for (int k = lane; k < nkb; k += 32) {
                float e = __expf(row[k] - m);
                row[k] = e;
                sum += e;
            }
#pragma unroll
            for (int o = 16; o; o >>= 1) sum += __shfl_xor_sync(0xffffffffu, sum, o);
            const float inv = 1.0f / sum;
            float* gw = attw + ((size_t)bh * SS + (q0 + r)) * SS;
            for (int k4 = lane; k4 < nkb / 4; k4 += 32) {
                float4 p = *(float4*)&row[k4 * 4];
                p.x *= inv; p.y *= inv; p.z *= inv; p.w *= inv;
                *(float4*)&row[k4 * 4] = p;
                *(float4*)&gw[k4 * 4] = p;
            }
            const float4 z = make_float4(0.f, 0.f, 0.f, 0.f);
            for (int k4 = nkb / 4 + lane; k4 < SS / 4; k4 += 32)
                *(float4*)&gw[k4 * 4] = z;
        }
    }

    // --- phase 3: O = P @ V -> g_ctx ---
    {
        const int q = tid >> 4;
        const int d4 = (tid & 15) * 4;
        float4 o = make_float4(0.f, 0.f, 0.f, 0.f);
        for (int kt = 0; kt < nkb; kt += KT) {
            __syncthreads();   // covers softmax->PV ordering and sKV reuse
#pragma unroll
            for (int t = 0; t < 4; t++) {
                const int idx = tid + t * 256;
                const int r = idx >> 4, c4 = (idx & 15) * 4;
                float4 v4 = *(const float4*)(Vb + (size_t)(kt + r) * HD + c4);
                *(float4*)&sKV[r * KVP + c4] = v4;
            }
            __syncthreads();
#pragma unroll
            for (int kk4 = 0; kk4 < 16; kk4++) {
                float4 p = *(const float4*)&sS[q * SS + kt + kk4 * 4];
                float4 v0 = *(const float4*)&sKV[(kk4 * 4 + 0) * KVP + d4];
                float4 v1 = *(const float4*)&sKV[(kk4 * 4 + 1) * KVP + d4];
                float4 v2 = *(const float4*)&sKV[(kk4 * 4 + 2) * KVP + d4];
                float4 v3 = *(const float4*)&sKV[(kk4 * 4 + 3) * KVP + d4];
                o.x += p.x * v0.x + p.y * v1.x + p.z * v2.x + p.w * v3.x;
                o.y += p.x * v0.y + p.y * v1.y + p.z * v2.y + p.w * v3.y;
                o.z += p.x * v0.z + p.y * v1.z + p.z * v2.z + p.w * v3.z;
                o.w += p.x * v0.w + p.y * v1.w + p.z * v2.w + p.w * v3.w;
            }
        }
        // g_ctx[b, q0+q, h*64 + d4 .. +3]
        *(float4*)&g_ctx[((size_t)b_ * SS + (q0 + q)) * DD + h_ * HD + d4] = o;
    }
}

// ============================================================
// launch  (no static guards: identical work on every call)
// ============================================================
extern "C" void kernel_launch(void* const* d_in, const int* in_sizes, int n_in,
                              void* d_out, int out_size)
{
    const float* hs = (const float*)d_in[0];
    const float* wq = (const float*)d_in[1];
    const float* bq = (const float*)d_in[2];
    const float* wk = (const float*)d_in[3];
    const float* bk = (const float*)d_in[4];
    const float* wv = (const float*)d_in[5];
    const float* bv = (const float*)d_in[6];
    const float* wc = (const float*)d_in[7];
    const float* bc = (const float*)d_in[8];

    float* out      = (float*)d_out;
    float* attn_out = out;                                   // [2,2048,1024]
    float* attw     = out + (size_t)4194304;                 // [2,16,2048,2048]
    float* kout     = out + (size_t)4194304 + 134217728;     // [2,16,2048,64]
    float* vout     = kout + (size_t)4194304;                // [2,16,2048,64]

    // Unconditional (idempotent, capture-safe, deterministic).
    cudaFuncSetAttribute(attn_kernel,
                         cudaFuncAttributeMaxDynamicSharedMemorySize, ATTN_SMEM);

    dim3 gg(DD / 128, (BB * SS) / 128);   // (8, 32)
    gemm_bias<<<gg, 256>>>(hs, wq, bq, nullptr, 0);   // Q -> g_Q
    gemm_bias<<<gg, 256>>>(hs, wk, bk, kout, 3);      // K -> d_out region
    gemm_bias<<<gg, 256>>>(hs, wv, bv, vout, 3);      // V -> d_out region

    attn_kernel<<<dim3(SS / QB, BB * HH), 256, ATTN_SMEM>>>(kout, vout, attw);

    gemm_bias<<<gg, 256>>>(nullptr, wc, bc, attn_out, 2);  // g_ctx @ wc -> attn_out
}

// round 5
// speedup vs baseline: 1.2527x; 1.2527x over previous
#include <cuda_runtime.h>

#define BB 2
#define SS 2048
#define DD 1024
#define HH 16
#define HD 64
#define MASKV (-10000.0f)
#define SCALE 0.125f

// ---- scratch (allocation-free __device__ globals, referenced directly) ----
__device__ float g_Q[BB * HH * SS * HD];     // 16 MB, [b,h,s,hd]
__device__ float g_ctx[BB * SS * DD];        // 16 MB, [b,s,d]

// ============================================================
// GEMM: Y = X @ W + bias. (unchanged, near FMA roofline)
// mode 0: Y -> g_Q             in [b,h,s,hd] head layout
// mode 2: X = g_ctx, Y -> Yout plain [M,N]
// mode 3: Y -> Yout            in [b,h,s,hd] head layout
// ============================================================
__global__ __launch_bounds__(256) void gemm_bias(
    const float* __restrict__ Xin, const float* __restrict__ W,
    const float* __restrict__ bias, float* __restrict__ Yout, int mode)
{
    __shared__ float As[8][132];
    __shared__ float Bs[8][128];

    const float* X = (mode == 2) ? g_ctx : Xin;

    const int tid = threadIdx.x;
    const int bm = blockIdx.y * 128;
    const int bn = blockIdx.x * 128;
    const int tx = tid & 15, ty = tid >> 4;
    const int tm = ty * 8, tn = tx * 8;

    const int arow = tid >> 1, acol = (tid & 1) * 4;
    const int brow = tid >> 5, bcol = (tid & 31) * 4;

    float acc[8][8];
#pragma unroll
    for (int i = 0; i < 8; i++)
#pragma unroll
        for (int j = 0; j < 8; j++) acc[i][j] = 0.0f;

    const float* Aptr = X + (size_t)(bm + arow) * DD + acol;
    const float* Bptr = W + (size_t)brow * DD + bn + bcol;

    for (int k0 = 0; k0 < DD; k0 += 8) {
        float4 a4 = *(const float4*)(Aptr + k0);
        float4 b4 = *(const float4*)(Bptr + (size_t)k0 * DD);
        __syncthreads();
        As[acol + 0][arow] = a4.x;
        As[acol + 1][arow] = a4.y;
        As[acol + 2][arow] = a4.z;
        As[acol + 3][arow] = a4.w;
        *(float4*)&Bs[brow][bcol] = b4;
        __syncthreads();
#pragma unroll
        for (int k = 0; k < 8; k++) {
            float a[8], b[8];
            *(float4*)(a + 0) = *(const float4*)&As[k][tm];
            *(float4*)(a + 4) = *(const float4*)&As[k][tm + 4];
            *(float4*)(b + 0) = *(const float4*)&Bs[k][tn];
            *(float4*)(b + 4) = *(const float4*)&Bs[k][tn + 4];
#pragma unroll
            for (int i = 0; i < 8; i++)
#pragma unroll
                for (int j = 0; j < 8; j++)
                    acc[i][j] += a[i] * b[j];
        }
    }

    float* Y = (mode == 0) ? g_Q : Yout;

#pragma unroll
    for (int i = 0; i < 8; i++) {
        const int m = bm + tm + i;
        const int b_ = m >> 11;
        const int s_ = m & (SS - 1);
#pragma unroll
        for (int j = 0; j < 8; j++) {
            const int n = bn + tn + j;
            const float v = acc[i][j] + bias[n];
            if (mode == 0 || mode == 3) {
                const int h_ = n >> 6, d_ = n & 63;
                Y[(((size_t)(b_ * HH + h_) * SS) + s_) * HD + d_] = v;
            } else {
                Y[(size_t)m * DD + n] = v;
            }
        }
    }
}

// ============================================================
// Attention: per block = one (b,h) and 16 queries.
// Register-tiled for 8:1 FFMA:LDS.128 balance.
// smem: scores[16][2048] + KV tile [256][68] + Q tile [16][68]  = ~200 KB
// ============================================================
#define QB 16
#define KT 256
#define KVP 68
#define ATTN_SMEM ((QB * SS + KT * KVP + QB * KVP) * 4)

__global__ __launch_bounds__(256) void attn_kernel(
    const float* __restrict__ K, const float* __restrict__ V,
    float* __restrict__ attw)
{
    extern __shared__ float smem[];
    float* sS  = smem;                       // 16 x 2048
    float* sKV = smem + QB * SS;             // 256 x 68 (reused as reduction scratch)
    float* sQ  = sKV + KT * KVP;             // 16 x 68

    const int tid = threadIdx.x;
    const int bh = blockIdx.y;               // b*H + h
    const int b_ = bh >> 4, h_ = bh & 15;
    const int q0 = blockIdx.x * QB;

    const float* Qb = g_Q + ((size_t)bh * SS + q0) * HD;
    const float* Kb = K + (size_t)bh * SS * HD;
    const float* Vb = V + (size_t)bh * SS * HD;

    const int nkb = ((q0 + QB - 1) / KT + 1) * KT;   // causal key extent (tile granular)

    // --- load Q tile [16][64] -> sQ (padded rows) ---
    {
        const int r = tid >> 4, c4 = (tid & 15) * 4;
        float4 v4 = *(const float4*)(Qb + (size_t)r * HD + c4);
        *(float4*)&sQ[r * KVP + c4] = v4;
    }

    // --- phase 1: scores = Q K^T * scale, causal mask, into sS ---
    // Thread tile: 4 queries x 4 keys. 8 LDS.128 per 64 FFMA per d4 step.
    {
        const int qg = tid >> 6;         // 0..3  -> queries qg*4 .. qg*4+3
        const int kl = tid & 63;         // keys kl + 64*j, j=0..3
        for (int kt = 0; kt < nkb; kt += KT) {
            __syncthreads();
            // load K tile [256][64] -> sKV (16 float4 per thread)
#pragma unroll
            for (int t = 0; t < 16; t++) {
                const int idx = tid + t * 256;
                const int r = idx >> 4, c4 = (idx & 15) * 4;
                float4 v4 = *(const float4*)(Kb + (size_t)(kt + r) * HD + c4);
                *(float4*)&sKV[r * KVP + c4] = v4;
            }
            __syncthreads();

            float acc[4][4];
#pragma unroll
            for (int i = 0; i < 4; i++)
#pragma unroll
                for (int j = 0; j < 4; j++) acc[i][j] = 0.0f;

#pragma unroll
            for (int d4 = 0; d4 < 16; d4++) {
                float4 qv[4], kv[4];
#pragma unroll
                for (int i = 0; i < 4; i++)
                    qv[i] = *(const float4*)&sQ[(qg * 4 + i) * KVP + d4 * 4];
#pragma unroll
                for (int j = 0; j < 4; j++)
                    kv[j] = *(const float4*)&sKV[(kl + 64 * j) * KVP + d4 * 4];
#pragma unroll
                for (int i = 0; i < 4; i++)
#pragma unroll
                    for (int j = 0; j < 4; j++)
                        acc[i][j] += qv[i].x * kv[j].x + qv[i].y * kv[j].y
                                   + qv[i].z * kv[j].z + qv[i].w * kv[j].w;
            }

#pragma unroll
            for (int i = 0; i < 4; i++) {
                const int qglob = q0 + qg * 4 + i;
                float* srow = sS + (qg * 4 + i) * SS;
#pragma unroll
                for (int j = 0; j < 4; j++) {
                    const int kg = kt + kl + 64 * j;
                    srow[kg] = (kg > qglob) ? MASKV : acc[i][j] * SCALE;
                }
            }
        }
    }
    __syncthreads();

    // --- phase 2: softmax per row + write attn_weights ---
    {
        const int warp = tid >> 5, lane = tid & 31;
        for (int r = warp * 2; r < warp * 2 + 2; r++) {
            float* row = sS + r * SS;
            float m = -1e30f;
            for (int k = lane; k < nkb; k += 32) m = fmaxf(m, row[k]);
#pragma unroll
            for (int o = 16; o; o >>= 1) m = fmaxf(m, __shfl_xor_sync(0xffffffffu, m, o));
            float sum = 0.f;
            for (int k = lane; k < nkb; k += 32) {
                float e = __expf(row[k] - m);
                row[k] = e;
                sum += e;
            }
#pragma unroll
            for (int o = 16; o; o >>= 1) sum += __shfl_xor_sync(0xffffffffu, sum, o);
            const float inv = 1.0f / sum;
            float* gw = attw + ((size_t)bh * SS + (q0 + r)) * SS;
            for (int k4 = lane; k4 < nkb / 4; k4 += 32) {
                float4 p = *(float4*)&row[k4 * 4];
                p.x *= inv; p.y *= inv; p.z *= inv; p.w *= inv;
                *(float4*)&row[k4 * 4] = p;
                *(float4*)&gw[k4 * 4] = p;
            }
            const float4 z = make_float4(0.f, 0.f, 0.f, 0.f);
            for (int k4 = nkb / 4 + lane; k4 < SS / 4; k4 += 32)
                *(float4*)&gw[k4 * 4] = z;
        }
    }

    // --- phase 3: O = P @ V -> g_ctx ---
    // Thread tile: 4 queries x (1 float4 of d) x k-slice (4-way split).
    // 8 LDS.128 per 64 FFMA; partials reduced via smem.
    {
        const int ks  = tid >> 6;        // k-slice 0..3
        const int rem = tid & 63;
        const int qg  = rem >> 4;        // 0..3 -> queries qg*4..+3
        const int dl  = rem & 15;
        const int d4  = dl * 4;

        float4 o[4];
#pragma unroll
        for (int i = 0; i < 4; i++) o[i] = make_float4(0.f, 0.f, 0.f, 0.f);

        for (int kt = 0; kt < nkb; kt += KT) {
            __syncthreads();   // covers softmax->PV ordering and sKV reuse
#pragma unroll
            for (int t = 0; t < 16; t++) {
                const int idx = tid + t * 256;
                const int r = idx >> 4, c4 = (idx & 15) * 4;
                float4 v4 = *(const float4*)(Vb + (size_t)(kt + r) * HD + c4);
                *(float4*)&sKV[r * KVP + c4] = v4;
            }
            __syncthreads();

            for (int t = 0; t < KT / 16; t++) {
                const int kk4 = ks + t * 4;          // this slice's 4-key group
                float4 p[4], v[4];
#pragma unroll
                for (int i = 0; i < 4; i++)
                    p[i] = *(const float4*)&sS[(qg * 4 + i) * SS + kt + kk4 * 4];
#pragma unroll
                for (int r = 0; r < 4; r++)
                    v[r] = *(const float4*)&sKV[(kk4 * 4 + r) * KVP + d4];
#pragma unroll
                for (int i = 0; i < 4; i++) {
                    o[i].x += p[i].x * v[0].x + p[i].y * v[1].x + p[i].z * v[2].x + p[i].w * v[3].x;
                    o[i].y += p[i].x * v[0].y + p[i].y * v[1].y + p[i].z * v[2].y + p[i].w * v[3].y;
                    o[i].z += p[i].x * v[0].z + p[i].y * v[1].z + p[i].z * v[2].z + p[i].w * v[3].z;
                    o[i].w += p[i].x * v[0].w + p[i].y * v[1].w + p[i].z * v[2].w + p[i].w * v[3].w;
                }
            }
        }

        // reduce 4 k-slices via smem (reuse sKV as scratch: 64 q-units x 16 dl x float4)
        __syncthreads();                 // all slices done reading V
#pragma unroll
        for (int i = 0; i < 4; i++)
            *(float4*)&sKV[(((ks * 16) + (qg * 4 + i)) * 16 + dl) * 4] = o[i];
        __syncthreads();

        {
            const int q  = tid >> 4;     // 0..15
            const int dl2 = tid & 15;
            float4 r0 = *(const float4*)&sKV[((0 * 16 + q) * 16 + dl2) * 4];
            float4 r1 = *(const float4*)&sKV[((1 * 16 + q) * 16 + dl2) * 4];
            float4 r2 = *(const float4*)&sKV[((2 * 16 + q) * 16 + dl2) * 4];
            float4 r3 = *(const float4*)&sKV[((3 * 16 + q) * 16 + dl2) * 4];
            float4 s;
            s.x = r0.x + r1.x + r2.x + r3.x;
            s.y = r0.y + r1.y + r2.y + r3.y;
            s.z = r0.z + r1.z + r2.z + r3.z;
            s.w = r0.w + r1.w + r2.w + r3.w;
            *(float4*)&g_ctx[((size_t)b_ * SS + (q0 + q)) * DD + h_ * HD + dl2 * 4] = s;
        }
    }
}

// ============================================================
// launch  (no static guards: identical work on every call)
// ============================================================
extern "C" void kernel_launch(void* const* d_in, const int* in_sizes, int n_in,
                              void* d_out, int out_size)
{
    const float* hs = (const float*)d_in[0];
    const float* wq = (const float*)d_in[1];
    const float* bq = (const float*)d_in[2];
    const float* wk = (const float*)d_in[3];
    const float* bk = (const float*)d_in[4];
    const float* wv = (const float*)d_in[5];
    const float* bv = (const float*)d_in[6];
    const float* wc = (const float*)d_in[7];
    const float* bc = (const float*)d_in[8];

    float* out      = (float*)d_out;
    float* attn_out = out;                                   // [2,2048,1024]
    float* attw     = out + (size_t)4194304;                 // [2,16,2048,2048]
    float* kout     = out + (size_t)4194304 + 134217728;     // [2,16,2048,64]
    float* vout     = kout + (size_t)4194304;                // [2,16,2048,64]

    cudaFuncSetAttribute(attn_kernel,
                         cudaFuncAttributeMaxDynamicSharedMemorySize, ATTN_SMEM);

    dim3 gg(DD / 128, (BB * SS) / 128);   // (8, 32)
    gemm_bias<<<gg, 256>>>(hs, wq, bq, nullptr, 0);   // Q -> g_Q
    gemm_bias<<<gg, 256>>>(hs, wk, bk, kout, 3);      // K -> d_out region
    gemm_bias<<<gg, 256>>>(hs, wv, bv, vout, 3);      // V -> d_out region

    attn_kernel<<<dim3(SS / QB, BB * HH), 256, ATTN_SMEM>>>(kout, vout, attw);

    gemm_bias<<<gg, 256>>>(nullptr, wc, bc, attn_out, 2);  // g_ctx @ wc -> attn_out
}

// round 8
// speedup vs baseline: 1.4026x; 1.1197x over previous
#include <cuda_runtime.h>

#define BB 2
#define SS 2048
#define DD 1024
#define HH 16
#define HD 64
#define MASKV (-10000.0f)
#define SCALE 0.125f

typedef unsigned long long u64;

// ---- f32x2 packed-FMA helpers (sm_103a; exact fp32 semantics) ----
__device__ __forceinline__ u64 ffma2(u64 a, u64 b, u64 c) {
    u64 d;
    asm("fma.rn.f32x2 %0, %1, %2, %3;" : "=l"(d) : "l"(a), "l"(b), "l"(c));
    return d;
}
__device__ __forceinline__ u64 pack2r(float v) {   // replicate v into both halves
    u64 r;
    asm("mov.b64 %0, {%1, %1};" : "=l"(r) : "f"(v));
    return r;
}
__device__ __forceinline__ float2 unpack2(u64 v) {
    float2 f;
    asm("mov.b64 {%0, %1}, %2;" : "=f"(f.x), "=f"(f.y) : "l"(v));
    return f;
}

// ---- scratch (allocation-free __device__ globals, referenced directly) ----
__device__ float g_Q[BB * HH * SS * HD];     // 16 MB, [b,h,s,hd]
__device__ float g_ctx[BB * SS * DD];        // 16 MB, [b,s,d]

// ============================================================
// GEMM: Y = X @ W + bias, f32x2 inner product (acc paired along n).
// mode 0: Y -> g_Q             in [b,h,s,hd] head layout
// mode 2: X = g_ctx, Y -> Yout plain [M,N]
// mode 3: Y -> Yout            in [b,h,s,hd] head layout
// Tile 128x128, BK=8, 256 threads, 8x8 micro-tile (as 8x4 f32x2).
// ============================================================
__global__ __launch_bounds__(256) void gemm_bias(
    const float* __restrict__ Xin, const float* __restrict__ W,
    const float* __restrict__ bias, float* __restrict__ Yout, int mode)
{
    __shared__ __align__(16) float As[8][132];
    __shared__ __align__(16) float Bs[8][128];

    const float* X = (mode == 2) ? g_ctx : Xin;

    const int tid = threadIdx.x;
    const int bm = blockIdx.y * 128;
    const int bn = blockIdx.x * 128;
    const int tx = tid & 15, ty = tid >> 4;
    const int tm = ty * 8, tn = tx * 8;

    const int arow = tid >> 1, acol = (tid & 1) * 4;
    const int brow = tid >> 5, bcol = (tid & 31) * 4;

    u64 acc[8][4];
#pragma unroll
    for (int i = 0; i < 8; i++)
#pragma unroll
        for (int j = 0; j < 4; j++) acc[i][j] = 0ull;

    const float* Aptr = X + (size_t)(bm + arow) * DD + acol;
    const float* Bptr = W + (size_t)brow * DD + bn + bcol;

    for (int k0 = 0; k0 < DD; k0 += 8) {
        float4 a4 = *(const float4*)(Aptr + k0);
        float4 b4 = *(const float4*)(Bptr + (size_t)k0 * DD);
        __syncthreads();
        As[acol + 0][arow] = a4.x;
        As[acol + 1][arow] = a4.y;
        As[acol + 2][arow] = a4.z;
        As[acol + 3][arow] = a4.w;
        *(float4*)&Bs[brow][bcol] = b4;
        __syncthreads();
#pragma unroll
        for (int k = 0; k < 8; k++) {
            float a[8];
            *(float4*)(a + 0) = *(const float4*)&As[k][tm];
            *(float4*)(a + 4) = *(const float4*)&As[k][tm + 4];
            ulonglong2 b01 = *(const ulonglong2*)&Bs[k][tn];
            ulonglong2 b23 = *(const ulonglong2*)&Bs[k][tn + 4];
            u64 a2[8];
#pragma unroll
            for (int i = 0; i < 8; i++) a2[i] = pack2r(a[i]);
#pragma unroll
            for (int i = 0; i < 8; i++) {
                acc[i][0] = ffma2(a2[i], b01.x, acc[i][0]);
                acc[i][1] = ffma2(a2[i], b01.y, acc[i][1]);
                acc[i][2] = ffma2(a2[i], b23.x, acc[i][2]);
                acc[i][3] = ffma2(a2[i], b23.y, acc[i][3]);
            }
        }
    }

    float* Y = (mode == 0) ? g_Q : Yout;

#pragma unroll
    for (int i = 0; i < 8; i++) {
        const int m = bm + tm + i;
        const int b_ = m >> 11;
        const int s_ = m & (SS - 1);
#pragma unroll
        for (int j = 0; j < 4; j++) {
            float2 p = unpack2(acc[i][j]);
            const int n0 = bn + tn + 2 * j;
            const float v0 = p.x + bias[n0];
            const float v1 = p.y + bias[n0 + 1];
            if (mode == 0 || mode == 3) {
                const int h_ = n0 >> 6, d_ = n0 & 63;
                float* dst = &Y[(((size_t)(b_ * HH + h_) * SS) + s_) * HD + d_];
                dst[0] = v0;
                dst[1] = v1;     // n0, n0+1 share head (HD=64, 2j aligned)
            } else {
                Y[(size_t)m * DD + n0] = v0;
                Y[(size_t)m * DD + n0 + 1] = v1;
            }
        }
    }
}

// ============================================================
// Attention: per block = one (b,h) and 16 queries, f32x2 math.
// smem: scores[16][2048] + KV tile [256][68] + Q tile [16][68]  = ~200 KB
// ============================================================
#define QB 16
#define KT 256
#define KVP 68
#define ATTN_SMEM ((QB * SS + KT * KVP + QB * KVP) * 4)

__global__ __launch_bounds__(256) void attn_kernel(
    const float* __restrict__ K, const float* __restrict__ V,
    float* __restrict__ attw)
{
    extern __shared__ __align__(16) float smem[];
    float* sS  = smem;                       // 16 x 2048
    float* sKV = smem + QB * SS;             // 256 x 68 (reused as reduction scratch)
    float* sQ  = sKV + KT * KVP;             // 16 x 68

    const int tid = threadIdx.x;
    const int bh = blockIdx.y;               // b*H + h
    const int b_ = bh >> 4, h_ = bh & 15;
    const int q0 = blockIdx.x * QB;

    const float* Qb = g_Q + ((size_t)bh * SS + q0) * HD;
    const float* Kb = K + (size_t)bh * SS * HD;
    const float* Vb = V + (size_t)bh * SS * HD;

    const int nkb = ((q0 + QB - 1) / KT + 1) * KT;   // causal key extent

    // --- load Q tile [16][64] -> sQ (padded rows) ---
    {
        const int r = tid >> 4, c4 = (tid & 15) * 4;
        float4 v4 = *(const float4*)(Qb + (size_t)r * HD + c4);
        *(float4*)&sQ[r * KVP + c4] = v4;
    }

    // --- phase 1: scores = Q K^T * scale, causal mask, into sS ---
    // 4q x 4k tile, f32x2 paired along d (even/odd partial sums).
    {
        const int qg = tid >> 6;         // 0..3  -> queries qg*4 .. qg*4+3
        const int kl = tid & 63;         // keys kl + 64*j, j=0..3
        for (int kt = 0; kt < nkb; kt += KT) {
            __syncthreads();
#pragma unroll
            for (int t = 0; t < 16; t++) {
                const int idx = tid + t * 256;
                const int r = idx >> 4, c4 = (idx & 15) * 4;
                float4 v4 = *(const float4*)(Kb + (size_t)(kt + r) * HD + c4);
                *(float4*)&sKV[r * KVP + c4] = v4;
            }
            __syncthreads();

            u64 acc2[4][4];
#pragma unroll
            for (int i = 0; i < 4; i++)
#pragma unroll
                for (int j = 0; j < 4; j++) acc2[i][j] = 0ull;

#pragma unroll
            for (int d4 = 0; d4 < 16; d4++) {
                ulonglong2 qp[4], kp[4];
#pragma unroll
                for (int i = 0; i < 4; i++)
                    qp[i] = *(const ulonglong2*)&sQ[(qg * 4 + i) * KVP + d4 * 4];
#pragma unroll
                for (int j = 0; j < 4; j++)
                    kp[j] = *(const ulonglong2*)&sKV[(kl + 64 * j) * KVP + d4 * 4];
#pragma unroll
                for (int i = 0; i < 4; i++)
#pragma unroll
                    for (int j = 0; j < 4; j++) {
                        acc2[i][j] = ffma2(qp[i].x, kp[j].x, acc2[i][j]);
                        acc2[i][j] = ffma2(qp[i].y, kp[j].y, acc2[i][j]);
                    }
            }

#pragma unroll
            for (int i = 0; i < 4; i++) {
                const int qglob = q0 + qg * 4 + i;
                float* srow = sS + (qg * 4 + i) * SS;
#pragma unroll
                for (int j = 0; j < 4; j++) {
                    const int kg = kt + kl + 64 * j;
                    float2 s = unpack2(acc2[i][j]);
                    srow[kg] = (kg > qglob) ? MASKV : (s.x + s.y) * SCALE;
                }
            }
        }
    }
    __syncthreads();

    // --- phase 2: softmax per row + write attn_weights ---
    {
        const int warp = tid >> 5, lane = tid & 31;
        for (int r = warp * 2; r < warp * 2 + 2; r++) {
            float* row = sS + r * SS;
            float m = -1e30f;
            for (int k = lane; k < nkb; k += 32) m = fmaxf(m, row[k]);
#pragma unroll
            for (int o = 16; o; o >>= 1) m = fmaxf(m, __shfl_xor_sync(0xffffffffu, m, o));
            float sum = 0.f;
            for (int k = lane; k < nkb; k += 32) {
                float e = __expf(row[k] - m);
                row[k] = e;
                sum += e;
            }
#pragma unroll
            for (int o = 16; o; o >>= 1) sum += __shfl_xor_sync(0xffffffffu, sum, o);
            const float inv = 1.0f / sum;
            float* gw = attw + ((size_t)bh * SS + (q0 + r)) * SS;
            for (int k4 = lane; k4 < nkb / 4; k4 += 32) {
                float4 p = *(float4*)&row[k4 * 4];
                p.x *= inv; p.y *= inv; p.z *= inv; p.w *= inv;
                *(float4*)&row[k4 * 4] = p;
                *(float4*)&gw[k4 * 4] = p;
            }
            const float4 z = make_float4(0.f, 0.f, 0.f, 0.f);
            for (int k4 = nkb / 4 + lane; k4 < SS / 4; k4 += 32)
                *(float4*)&gw[k4 * 4] = z;
        }
    }

    // --- phase 3: O = P @ V -> g_ctx ---
    // 4q x float4-of-d x 4-way k-slice, f32x2 paired along d.
    {
        const int ks  = tid >> 6;        // k-slice 0..3
        const int rem = tid & 63;
        const int qg  = rem >> 4;        // 0..3 -> queries qg*4..+3
        const int dl  = rem & 15;
        const int d4  = dl * 4;

        u64 o2[4][2];
#pragma unroll
        for (int i = 0; i < 4; i++) { o2[i][0] = 0ull; o2[i][1] = 0ull; }

        for (int kt = 0; kt < nkb; kt += KT) {
            __syncthreads();   // covers softmax->PV ordering and sKV reuse
#pragma unroll
            for (int t = 0; t < 16; t++) {
                const int idx = tid + t * 256;
                const int r = idx >> 4, c4 = (idx & 15) * 4;
                float4 v4 = *(const float4*)(Vb + (size_t)(kt + r) * HD + c4);
                *(float4*)&sKV[r * KVP + c4] = v4;
            }
            __syncthreads();

            for (int t = 0; t < KT / 16; t++) {
                const int kk4 = ks + t * 4;          // this slice's 4-key group
                float4 p[4];
                ulonglong2 v2[4];
#pragma unroll
                for (int i = 0; i < 4; i++)
                    p[i] = *(const float4*)&sS[(qg * 4 + i) * SS + kt + kk4 * 4];
#pragma unroll
                for (int r = 0; r < 4; r++)
                    v2[r] = *(const ulonglong2*)&sKV[(kk4 * 4 + r) * KVP + d4];
#pragma unroll
                for (int i = 0; i < 4; i++) {
                    u64 px = pack2r(p[i].x), py = pack2r(p[i].y);
                    u64 pz = pack2r(p[i].z), pw = pack2r(p[i].w);
                    o2[i][0] = ffma2(px, v2[0].x, o2[i][0]);
                    o2[i][0] = ffma2(py, v2[1].x, o2[i][0]);
                    o2[i][0] = ffma2(pz, v2[2].x, o2[i][0]);
                    o2[i][0] = ffma2(pw, v2[3].x, o2[i][0]);
                    o2[i][1] = ffma2(px, v2[0].y, o2[i][1]);
                    o2[i][1] = ffma2(py, v2[1].y, o2[i][1]);
                    o2[i][1] = ffma2(pz, v2[2].y, o2[i][1]);
                    o2[i][1] = ffma2(pw, v2[3].y, o2[i][1]);
                }
            }
        }

        // reduce 4 k-slices via smem (reuse sKV as scratch)
        __syncthreads();                 // all slices done reading V
#pragma unroll
        for (int i = 0; i < 4; i++) {
            float2 lo = unpack2(o2[i][0]);
            float2 hi = unpack2(o2[i][1]);
            float4 o = make_float4(lo.x, lo.y, hi.x, hi.y);
            *(float4*)&sKV[(((ks * 16) + (qg * 4 + i)) * 16 + dl) * 4] = o;
        }
        __syncthreads();

        {
            const int q   = tid >> 4;    // 0..15
            const int dl2 = tid & 15;
            float4 r0 = *(const float4*)&sKV[((0 * 16 + q) * 16 + dl2) * 4];
            float4 r1 = *(const float4*)&sKV[((1 * 16 + q) * 16 + dl2) * 4];
            float4 r2 = *(const float4*)&sKV[((2 * 16 + q) * 16 + dl2) * 4];
            float4 r3 = *(const float4*)&sKV[((3 * 16 + q) * 16 + dl2) * 4];
            float4 s;
            s.x = r0.x + r1.x + r2.x + r3.x;
            s.y = r0.y + r1.y + r2.y + r3.y;
            s.z = r0.z + r1.z + r2.z + r3.z;
            s.w = r0.w + r1.w + r2.w + r3.w;
            *(float4*)&g_ctx[((size_t)b_ * SS + (q0 + q)) * DD + h_ * HD + dl2 * 4] = s;
        }
    }
}

// ============================================================
// launch  (no static guards: identical work on every call)
// ============================================================
extern "C" void kernel_launch(void* const* d_in, const int* in_sizes, int n_in,
                              void* d_out, int out_size)
{
    const float* hs = (const float*)d_in[0];
    const float* wq = (const float*)d_in[1];
    const float* bq = (const float*)d_in[2];
    const float* wk = (const float*)d_in[3];
    const float* bk = (const float*)d_in[4];
    const float* wv = (const float*)d_in[5];
    const float* bv = (const float*)d_in[6];
    const float* wc = (const float*)d_in[7];
    const float* bc = (const float*)d_in[8];

    float* out      = (float*)d_out;
    float* attn_out = out;                                   // [2,2048,1024]
    float* attw     = out + (size_t)4194304;                 // [2,16,2048,2048]
    float* kout     = out + (size_t)4194304 + 134217728;     // [2,16,2048,64]
    float* vout     = kout + (size_t)4194304;                // [2,16,2048,64]

    cudaFuncSetAttribute(attn_kernel,
                         cudaFuncAttributeMaxDynamicSharedMemorySize, ATTN_SMEM);

    dim3 gg(DD / 128, (BB * SS) / 128);   // (8, 32)
    gemm_bias<<<gg, 256>>>(hs, wq, bq, nullptr, 0);   // Q -> g_Q
    gemm_bias<<<gg, 256>>>(hs, wk, bk, kout, 3);      // K -> d_out region
    gemm_bias<<<gg, 256>>>(hs, wv, bv, vout, 3);      // V -> d_out region

    attn_kernel<<<dim3(SS / QB, BB * HH), 256, ATTN_SMEM>>>(kout, vout, attw);

    gemm_bias<<<gg, 256>>>(nullptr, wc, bc, attn_out, 2);  // g_ctx @ wc -> attn_out
}

// round 9
// speedup vs baseline: 2.0809x; 1.4836x over previous
#include <cuda_runtime.h>
#include <cuda_bf16.h>
#include <cstdint>

#define BB 2
#define SS 2048
#define DD 1024
#define HH 16
#define HD 64
#define MASKV (-10000.0f)
#define SCALE 0.125f

typedef unsigned long long u64;

// ---- f32x2 helpers (attention, unchanged) ----
__device__ __forceinline__ u64 ffma2(u64 a, u64 b, u64 c) {
    u64 d;
    asm("fma.rn.f32x2 %0, %1, %2, %3;" : "=l"(d) : "l"(a), "l"(b), "l"(c));
    return d;
}
__device__ __forceinline__ u64 pack2r(float v) {
    u64 r;
    asm("mov.b64 %0, {%1, %1};" : "=l"(r) : "f"(v));
    return r;
}
__device__ __forceinline__ float2 unpack2(u64 v) {
    float2 f;
    asm("mov.b64 {%0, %1}, %2;" : "=f"(f.x), "=f"(f.y) : "l"(v));
    return f;
}

// ---- tensor-core helpers ----
__device__ __forceinline__ void ldsm4(uint32_t* r, uint32_t addr) {
    asm volatile("ldmatrix.sync.aligned.m8n8.x4.shared.b16 {%0,%1,%2,%3}, [%4];"
        : "=r"(r[0]), "=r"(r[1]), "=r"(r[2]), "=r"(r[3]) : "r"(addr));
}
__device__ __forceinline__ void ldsm2t(uint32_t* r, uint32_t addr) {
    asm volatile("ldmatrix.sync.aligned.m8n8.x2.trans.shared.b16 {%0,%1}, [%2];"
        : "=r"(r[0]), "=r"(r[1]) : "r"(addr));
}
__device__ __forceinline__ void mma_bf16(float* d, const uint32_t* a, const uint32_t* b) {
    asm volatile("mma.sync.aligned.m16n8k16.row.col.f32.bf16.bf16.f32 "
        "{%0,%1,%2,%3}, {%4,%5,%6,%7}, {%8,%9}, {%0,%1,%2,%3};"
        : "+f"(d[0]), "+f"(d[1]), "+f"(d[2]), "+f"(d[3])
        : "r"(a[0]), "r"(a[1]), "r"(a[2]), "r"(a[3]), "r"(b[0]), "r"(b[1]));
}

// ---- scratch (allocation-free __device__ globals) ----
__device__ float g_Q[BB * HH * SS * HD];                  // fp32 Q, [b,h,s,hd]
__device__ float g_ctx[BB * SS * DD];                     // fp32 ctx, [b,s,d]
__device__ __nv_bfloat16 g_Xhi[BB * SS * DD];             // activations hi
__device__ __nv_bfloat16 g_Xlo[BB * SS * DD];             // activations lo
__device__ __nv_bfloat16 g_Whi[DD * DD];                  // weight hi (reused)
__device__ __nv_bfloat16 g_Wlo[DD * DD];                  // weight lo (reused)

// ============================================================
// split fp32 -> (hi, lo) bf16.  use_ctx: read from g_ctx instead of X.
// ============================================================
__global__ __launch_bounds__(256) void split_kernel(
    const float* __restrict__ X, __nv_bfloat16* __restrict__ Hi,
    __nv_bfloat16* __restrict__ Lo, int n4, int use_ctx)
{
    const float* src = use_ctx ? g_ctx : X;
    int i = blockIdx.x * 256 + threadIdx.x;
    if (i >= n4) return;
    float4 v = ((const float4*)src)[i];
    __nv_bfloat16 h0 = __float2bfloat16(v.x);
    __nv_bfloat16 h1 = __float2bfloat16(v.y);
    __nv_bfloat16 h2 = __float2bfloat16(v.z);
    __nv_bfloat16 h3 = __float2bfloat16(v.w);
    __nv_bfloat16 l0 = __float2bfloat16(v.x - __bfloat162float(h0));
    __nv_bfloat16 l1 = __float2bfloat16(v.y - __bfloat162float(h1));
    __nv_bfloat16 l2 = __float2bfloat16(v.z - __bfloat162float(h2));
    __nv_bfloat16 l3 = __float2bfloat16(v.w - __bfloat162float(h3));
    __nv_bfloat162* hp = (__nv_bfloat162*)&Hi[i * 4];
    __nv_bfloat162* lp = (__nv_bfloat162*)&Lo[i * 4];
    hp[0] = __nv_bfloat162(h0, h1);
    hp[1] = __nv_bfloat162(h2, h3);
    lp[0] = __nv_bfloat162(l0, l1);
    lp[1] = __nv_bfloat162(l2, l3);
}

// ============================================================
// Tensor-core GEMM: Y = X @ W + bias via bf16 hi/lo split.
// Reads g_Xhi/g_Xlo [M,K] and g_Whi/g_Wlo [K,N].
// mode 0: -> g_Q head layout; mode 3: -> Yout head layout; mode 2: -> Yout flat
// Tile 128x128x32, 8 warps, warp tile 64x32, m16n8k16.
// ============================================================
#define APAD 40     // bf16 row stride for A tiles
#define BPAD 136    // bf16 row stride for B tiles

__global__ __launch_bounds__(256) void gemm_tc(
    const float* __restrict__ bias, float* __restrict__ Yout, int mode)
{
    __shared__ __nv_bfloat16 sAh[128 * APAD];
    __shared__ __nv_bfloat16 sAl[128 * APAD];
    __shared__ __nv_bfloat16 sBh[32 * BPAD];
    __shared__ __nv_bfloat16 sBl[32 * BPAD];

    const int tid  = threadIdx.x;
    const int warp = tid >> 5, lane = tid & 31;
    const int bm = blockIdx.y * 128, bn = blockIdx.x * 128;
    const int wm = (warp >> 2) * 64;   // warp row block
    const int wn = (warp & 3) * 32;    // warp col block

    float acc[4][4][4];
#pragma unroll
    for (int fm = 0; fm < 4; fm++)
#pragma unroll
        for (int fn = 0; fn < 4; fn++)
#pragma unroll
            for (int r = 0; r < 4; r++) acc[fm][fn][r] = 0.0f;

    const int arow0 = tid >> 2, acol = (tid & 3) * 8;    // A: 128x32, 16B chunks
    const int brow0 = tid >> 4, bcol = (tid & 15) * 8;   // B: 32x128, 16B chunks

    for (int k0 = 0; k0 < DD; k0 += 32) {
        __syncthreads();
#pragma unroll
        for (int i = 0; i < 2; i++) {
            const int r = arow0 + i * 64;
            *(uint4*)&sAh[r * APAD + acol] =
                *(const uint4*)&g_Xhi[(size_t)(bm + r) * DD + k0 + acol];
            *(uint4*)&sAl[r * APAD + acol] =
                *(const uint4*)&g_Xlo[(size_t)(bm + r) * DD + k0 + acol];
        }
#pragma unroll
        for (int i = 0; i < 2; i++) {
            const int r = brow0 + i * 16;
            *(uint4*)&sBh[r * BPAD + bcol] =
                *(const uint4*)&g_Whi[(size_t)(k0 + r) * DD + bn + bcol];
            *(uint4*)&sBl[r * BPAD + bcol] =
                *(const uint4*)&g_Wlo[(size_t)(k0 + r) * DD + bn + bcol];
        }
        __syncthreads();

#pragma unroll
        for (int kk = 0; kk < 2; kk++) {
            uint32_t ah[4][4], al[4][4], bh[4][2], bl[4][2];
            const int arow = (lane & 15), acol2 = kk * 16 + (lane >> 4) * 8;
#pragma unroll
            for (int fm = 0; fm < 4; fm++) {
                ldsm4(ah[fm], (uint32_t)__cvta_generic_to_shared(
                    &sAh[(wm + fm * 16 + arow) * APAD + acol2]));
                ldsm4(al[fm], (uint32_t)__cvta_generic_to_shared(
                    &sAl[(wm + fm * 16 + arow) * APAD + acol2]));
            }
            const int brow = kk * 16 + (lane & 15);
#pragma unroll
            for (int fn = 0; fn < 4; fn++) {
                ldsm2t(bh[fn], (uint32_t)__cvta_generic_to_shared(
                    &sBh[brow * BPAD + wn + fn * 8]));
                ldsm2t(bl[fn], (uint32_t)__cvta_generic_to_shared(
                    &sBl[brow * BPAD + wn + fn * 8]));
            }
#pragma unroll
            for (int fm = 0; fm < 4; fm++)
#pragma unroll
                for (int fn = 0; fn < 4; fn++) {
                    mma_bf16(acc[fm][fn], ah[fm], bh[fn]);
                    mma_bf16(acc[fm][fn], ah[fm], bl[fn]);
                    mma_bf16(acc[fm][fn], al[fm], bh[fn]);
                }
        }
    }

    // epilogue: c frag layout m16n8 (lane>>2 = row, (lane&3)*2 = col pair)
    const int gr = lane >> 2, gc = (lane & 3) * 2;
#pragma unroll
    for (int fm = 0; fm < 4; fm++)
#pragma unroll
        for (int fn = 0; fn < 4; fn++)
#pragma unroll
            for (int h = 0; h < 2; h++) {
                const int m = bm + wm + fm * 16 + gr + h * 8;
                const int n = bn + wn + fn * 8 + gc;
                float2 bv = *(const float2*)&bias[n];
                float2 w;
                w.x = acc[fm][fn][h * 2 + 0] + bv.x;
                w.y = acc[fm][fn][h * 2 + 1] + bv.y;
                const int b_ = m >> 11, s_ = m & (SS - 1);
                if (mode == 2) {
                    *(float2*)&Yout[(size_t)m * DD + n] = w;
                } else {
                    float* Y = (mode == 0) ? g_Q : Yout;
                    const int h_ = n >> 6, d_ = n & 63;
                    *(float2*)&Y[(((size_t)(b_ * HH + h_) * SS) + s_) * HD + d_] = w;
                }
            }
}

// ============================================================
// Attention (unchanged from round-8 passing version)
// ============================================================
#define QB 16
#define KT 256
#define KVP 68
#define ATTN_SMEM ((QB * SS + KT * KVP + QB * KVP) * 4)

__global__ __launch_bounds__(256) void attn_kernel(
    const float* __restrict__ K, const float* __restrict__ V,
    float* __restrict__ attw)
{
    extern __shared__ __align__(16) float smem[];
    float* sS  = smem;                       // 16 x 2048
    float* sKV = smem + QB * SS;             // 256 x 68
    float* sQ  = sKV + KT * KVP;             // 16 x 68

    const int tid = threadIdx.x;
    const int bh = blockIdx.y;
    const int b_ = bh >> 4, h_ = bh & 15;
    const int q0 = blockIdx.x * QB;

    const float* Qb = g_Q + ((size_t)bh * SS + q0) * HD;
    const float* Kb = K + (size_t)bh * SS * HD;
    const float* Vb = V + (size_t)bh * SS * HD;

    const int nkb = ((q0 + QB - 1) / KT + 1) * KT;

    {
        const int r = tid >> 4, c4 = (tid & 15) * 4;
        float4 v4 = *(const float4*)(Qb + (size_t)r * HD + c4);
        *(float4*)&sQ[r * KVP + c4] = v4;
    }

    {
        const int qg = tid >> 6;
        const int kl = tid & 63;
        for (int kt = 0; kt < nkb; kt += KT) {
            __syncthreads();
#pragma unroll
            for (int t = 0; t < 16; t++) {
                const int idx = tid + t * 256;
                const int r = idx >> 4, c4 = (idx & 15) * 4;
                float4 v4 = *(const float4*)(Kb + (size_t)(kt + r) * HD + c4);
                *(float4*)&sKV[r * KVP + c4] = v4;
            }
            __syncthreads();

            u64 acc2[4][4];
#pragma unroll
            for (int i = 0; i < 4; i++)
#pragma unroll
                for (int j = 0; j < 4; j++) acc2[i][j] = 0ull;

#pragma unroll
            for (int d4 = 0; d4 < 16; d4++) {
                ulonglong2 qp[4], kp[4];
#pragma unroll
                for (int i = 0; i < 4; i++)
                    qp[i] = *(const ulonglong2*)&sQ[(qg * 4 + i) * KVP + d4 * 4];
#pragma unroll
                for (int j = 0; j < 4; j++)
                    kp[j] = *(const ulonglong2*)&sKV[(kl + 64 * j) * KVP + d4 * 4];
#pragma unroll
                for (int i = 0; i < 4; i++)
#pragma unroll
                    for (int j = 0; j < 4; j++) {
                        acc2[i][j] = ffma2(qp[i].x, kp[j].x, acc2[i][j]);
                        acc2[i][j] = ffma2(qp[i].y, kp[j].y, acc2[i][j]);
                    }
            }

#pragma unroll
            for (int i = 0; i < 4; i++) {
                const int qglob = q0 + qg * 4 + i;
                float* srow = sS + (qg * 4 + i) * SS;
#pragma unroll
                for (int j = 0; j < 4; j++) {
                    const int kg = kt + kl + 64 * j;
                    float2 s = unpack2(acc2[i][j]);
                    srow[kg] = (kg > qglob) ? MASKV : (s.x + s.y) * SCALE;
                }
            }
        }
    }
    __syncthreads();

    {
        const int warp = tid >> 5, lane = tid & 31;
        for (int r = warp * 2; r < warp * 2 + 2; r++) {
            float* row = sS + r * SS;
            float m = -1e30f;
            for (int k = lane; k < nkb; k += 32) m = fmaxf(m, row[k]);
#pragma unroll
            for (int o = 16; o; o >>= 1) m = fmaxf(m, __shfl_xor_sync(0xffffffffu, m, o));
            float sum = 0.f;
            for (int k = lane; k < nkb; k += 32) {
                float e = __expf(row[k] - m);
                row[k] = e;
                sum += e;
            }
#pragma unroll
            for (int o = 16; o; o >>= 1) sum += __shfl_xor_sync(0xffffffffu, sum, o);
            const float inv = 1.0f / sum;
            float* gw = attw + ((size_t)bh * SS + (q0 + r)) * SS;
            for (int k4 = lane; k4 < nkb / 4; k4 += 32) {
                float4 p = *(float4*)&row[k4 * 4];
                p.x *= inv; p.y *= inv; p.z *= inv; p.w *= inv;
                *(float4*)&row[k4 * 4] = p;
                *(float4*)&gw[k4 * 4] = p;
            }
            const float4 z = make_float4(0.f, 0.f, 0.f, 0.f);
            for (int k4 = nkb / 4 + lane; k4 < SS / 4; k4 += 32)
                *(float4*)&gw[k4 * 4] = z;
        }
    }

    {
        const int ks  = tid >> 6;
        const int rem = tid & 63;
        const int qg  = rem >> 4;
        const int dl  = rem & 15;
        const int d4  = dl * 4;

        u64 o2[4][2];
#pragma unroll
        for (int i = 0; i < 4; i++) { o2[i][0] = 0ull; o2[i][1] = 0ull; }

        for (int kt = 0; kt < nkb; kt += KT) {
            __syncthreads();
#pragma unroll
            for (int t = 0; t < 16; t++) {
                const int idx = tid + t * 256;
                const int r = idx >> 4, c4 = (idx & 15) * 4;
                float4 v4 = *(const float4*)(Vb + (size_t)(kt + r) * HD + c4);
                *(float4*)&sKV[r * KVP + c4] = v4;
            }
            __syncthreads();

            for (int t = 0; t < KT / 16; t++) {
                const int kk4 = ks + t * 4;
                float4 p[4];
                ulonglong2 v2[4];
#pragma unroll
                for (int i = 0; i < 4; i++)
                    p[i] = *(const float4*)&sS[(qg * 4 + i) * SS + kt + kk4 * 4];
#pragma unroll
                for (int r = 0; r < 4; r++)
                    v2[r] = *(const ulonglong2*)&sKV[(kk4 * 4 + r) * KVP + d4];
#pragma unroll
                for (int i = 0; i < 4; i++) {
                    u64 px = pack2r(p[i].x), py = pack2r(p[i].y);
                    u64 pz = pack2r(p[i].z), pw = pack2r(p[i].w);
                    o2[i][0] = ffma2(px, v2[0].x, o2[i][0]);
                    o2[i][0] = ffma2(py, v2[1].x, o2[i][0]);
                    o2[i][0] = ffma2(pz, v2[2].x, o2[i][0]);
                    o2[i][0] = ffma2(pw, v2[3].x, o2[i][0]);
                    o2[i][1] = ffma2(px, v2[0].y, o2[i][1]);
                    o2[i][1] = ffma2(py, v2[1].y, o2[i][1]);
                    o2[i][1] = ffma2(pz, v2[2].y, o2[i][1]);
                    o2[i][1] = ffma2(pw, v2[3].y, o2[i][1]);
                }
            }
        }

        __syncthreads();
#pragma unroll
        for (int i = 0; i < 4; i++) {
            float2 lo = unpack2(o2[i][0]);
            float2 hi = unpack2(o2[i][1]);
            float4 o = make_float4(lo.x, lo.y, hi.x, hi.y);
            *(float4*)&sKV[(((ks * 16) + (qg * 4 + i)) * 16 + dl) * 4] = o;
        }
        __syncthreads();

        {
            const int q   = tid >> 4;
            const int dl2 = tid & 15;
            float4 r0 = *(const float4*)&sKV[((0 * 16 + q) * 16 + dl2) * 4];
            float4 r1 = *(const float4*)&sKV[((1 * 16 + q) * 16 + dl2) * 4];
            float4 r2 = *(const float4*)&sKV[((2 * 16 + q) * 16 + dl2) * 4];
            float4 r3 = *(const float4*)&sKV[((3 * 16 + q) * 16 + dl2) * 4];
            float4 s;
            s.x = r0.x + r1.x + r2.x + r3.x;
            s.y = r0.y + r1.y + r2.y + r3.y;
            s.z = r0.z + r1.z + r2.z + r3.z;
            s.w = r0.w + r1.w + r2.w + r3.w;
            *(float4*)&g_ctx[((size_t)b_ * SS + (q0 + q)) * DD + h_ * HD + dl2 * 4] = s;
        }
    }
}

// ============================================================
// launch  (no static guards: identical work on every call)
// ============================================================
extern "C" void kernel_launch(void* const* d_in, const int* in_sizes, int n_in,
                              void* d_out, int out_size)
{
    const float* hs = (const float*)d_in[0];
    const float* wq = (const float*)d_in[1];
    const float* bq = (const float*)d_in[2];
    const float* wk = (const float*)d_in[3];
    const float* bk = (const float*)d_in[4];
    const float* wv = (const float*)d_in[5];
    const float* bv = (const float*)d_in[6];
    const float* wc = (const float*)d_in[7];
    const float* bc = (const float*)d_in[8];

    float* out      = (float*)d_out;
    float* attn_out = out;                                   // [2,2048,1024]
    float* attw     = out + (size_t)4194304;                 // [2,16,2048,2048]
    float* kout     = out + (size_t)4194304 + 134217728;     // [2,16,2048,64]
    float* vout     = kout + (size_t)4194304;                // [2,16,2048,64]

    cudaFuncSetAttribute(attn_kernel,
                         cudaFuncAttributeMaxDynamicSharedMemorySize, ATTN_SMEM);

    __nv_bfloat16 *xhi = nullptr, *xlo = nullptr, *whi = nullptr, *wlo = nullptr;
    cudaGetSymbolAddress((void**)&xhi, g_Xhi);
    cudaGetSymbolAddress((void**)&xlo, g_Xlo);
    cudaGetSymbolAddress((void**)&whi, g_Whi);
    cudaGetSymbolAddress((void**)&wlo, g_Wlo);

    const int NX4 = BB * SS * DD / 4;   // 1M
    const int NW4 = DD * DD / 4;        // 256K
    dim3 gg(DD / 128, (BB * SS) / 128); // (8, 32)

    split_kernel<<<NX4 / 256, 256>>>(hs, xhi, xlo, NX4, 0);

    split_kernel<<<NW4 / 256, 256>>>(wq, whi, wlo, NW4, 0);
    gemm_tc<<<gg, 256>>>(bq, nullptr, 0);    // Q -> g_Q head layout

    split_kernel<<<NW4 / 256, 256>>>(wk, whi, wlo, NW4, 0);
    gemm_tc<<<gg, 256>>>(bk, kout, 3);       // K -> d_out head layout

    split_kernel<<<NW4 / 256, 256>>>(wv, whi, wlo, NW4, 0);
    gemm_tc<<<gg, 256>>>(bv, vout, 3);       // V -> d_out head layout

    attn_kernel<<<dim3(SS / QB, BB * HH), 256, ATTN_SMEM>>>(kout, vout, attw);

    split_kernel<<<NX4 / 256, 256>>>(nullptr, xhi, xlo, NX4, 1);  // g_ctx -> hi/lo
    split_kernel<<<NW4 / 256, 256>>>(wc, whi, wlo, NW4, 0);
    gemm_tc<<<gg, 256>>>(bc, attn_out, 2);   // c_proj -> flat
}